// round 13
// baseline (speedup 1.0000x reference)
#include <cuda_runtime.h>
#include <cstddef>

#define NN 50000
#define EE 800000
#define ENE (EE + NN)
#define SCAN_B 196   // ceil(NN/256)

// GEMM dynamic smem layout (words): As[2][128][36] then Bs[2][32][68]
#define AS_WORDS 4608        // 128*36
#define BS_WORDS 2176        // 32*68
#define SM_BS_BASE (2 * AS_WORDS)
#define GEMM_SMEM_BYTES ((2 * AS_WORDS + 2 * BS_WORDS) * 4)   // 54,272

// -------- scratch (static device globals; no allocation) --------
__device__ float g_bufA[NN * 256];   // GEMM output h per layer
__device__ float g_bufB[NN * 256];   // aggregation output / next-layer input
__device__ float g_as[NN * 4];
__device__ float g_ad[NN * 4];
__device__ float g_pool[64];
__device__ int g_is64;
__device__ int g_src[ENE];
__device__ int g_dst[ENE];
__device__ int g_cnt[NN];
__device__ int g_off[NN + 1];
__device__ int g_fill[NN];
__device__ int g_csrc[ENE];
__device__ int g_bsum[256];
__device__ int g_boff[256];

// -------- edge_index dtype detection --------
__global__ void detect_kernel(const int* __restrict__ ei32)
{
    __shared__ int sh[256];
    int acc = 0;
    for (int i = threadIdx.x; i < 65536; i += 256)
        acc |= ei32[2 * i + 1];
    sh[threadIdx.x] = acc;
    __syncthreads();
    for (int o = 128; o; o >>= 1) {
        if (threadIdx.x < o) sh[threadIdx.x] |= sh[threadIdx.x + o];
        __syncthreads();
    }
    if (threadIdx.x == 0) g_is64 = (sh[0] == 0) ? 1 : 0;
}

// -------- zero cnt + layer-0 alpha accumulators (one kernel) --------
__global__ void zero_cnt_alpha_kernel()
{
    int i = blockIdx.x * blockDim.x + threadIdx.x;
    if (i < NN) g_cnt[i] = 0;
    if (i < NN * 4) { g_as[i] = 0.f; g_ad[i] = 0.f; }
}

__global__ void zero_alpha_kernel(float* __restrict__ as_, float* __restrict__ ad_, int nh)
{
    int i = blockIdx.x * blockDim.x + threadIdx.x;
    if (i < nh) { as_[i] = 0.f; ad_[i] = 0.f; }
}

__global__ void decode_kernel(const int* __restrict__ ei32)
{
    int e = blockIdx.x * blockDim.x + threadIdx.x;
    if (e >= ENE) return;
    int s, d;
    if (e < EE) {
        if (g_is64) { s = ei32[2 * e]; d = ei32[2 * (EE + e)]; }
        else        { s = ei32[e];     d = ei32[EE + e]; }
        s = min(max(s, 0), NN - 1);
        d = min(max(d, 0), NN - 1);
    } else {
        s = d = e - EE;
    }
    g_src[e] = s;
    g_dst[e] = d;
    atomicAdd(&g_cnt[d], 1);
}

// 3-stage parallel exclusive scan of g_cnt -> g_off
__global__ void block_sum_kernel()
{
    __shared__ int sh[256];
    int t = threadIdx.x;
    int i = blockIdx.x * 256 + t;
    sh[t] = (i < NN) ? g_cnt[i] : 0;
    __syncthreads();
    for (int o = 128; o; o >>= 1) {
        if (t < o) sh[t] += sh[t + o];
        __syncthreads();
    }
    if (t == 0) g_bsum[blockIdx.x] = sh[0];
}

__global__ void scan_bsum_kernel()
{
    __shared__ int sh[256];
    int t = threadIdx.x;
    sh[t] = (t < SCAN_B) ? g_bsum[t] : 0;
    __syncthreads();
    for (int o = 1; o < 256; o <<= 1) {
        int u = (t >= o) ? sh[t - o] : 0;
        __syncthreads();
        sh[t] += u;
        __syncthreads();
    }
    g_boff[t] = t ? sh[t - 1] : 0;
    if (t == SCAN_B - 1) g_off[NN] = sh[t];
}

__global__ void scan_final_kernel()
{
    __shared__ int sh[256];
    int t = threadIdx.x;
    int i = blockIdx.x * 256 + t;
    int v = (i < NN) ? g_cnt[i] : 0;
    sh[t] = v;
    __syncthreads();
    for (int o = 1; o < 256; o <<= 1) {
        int u = (t >= o) ? sh[t - o] : 0;
        __syncthreads();
        sh[t] += u;
        __syncthreads();
    }
    if (i < NN) {
        int ex = sh[t] - v + g_boff[blockIdx.x];
        g_off[i] = ex;
        g_fill[i] = ex;
    }
}

__global__ void scatter_kernel()
{
    int e = blockIdx.x * blockDim.x + threadIdx.x;
    if (e >= ENE) return;
    int d = g_dst[e];
    int pos = atomicAdd(&g_fill[d], 1);
    g_csrc[pos] = g_src[e];
}

// -------- TF32 tensor-core GEMM + fused alpha epilogue, double-buffered --------
// C[M,Nc] = A[M,K] @ W[K,Nc]; BM=128, BN=64 (one head), BK=32.
// 8 warps as 4(M) x 2(N); warp tile 32x32 (mf=2, nf=4); mma m16n8k8.
// Conflict-free scalar-LDS fragment loads; STS.128 staging stores;
// register-prefetch + ping-pong smem hides gmem latency, 1 sync/k-tile.
__device__ __forceinline__ unsigned f2tf32(float f)
{
    unsigned u;
    asm("cvt.rna.tf32.f32 %0, %1;" : "=r"(u) : "f"(f));
    return u;
}

__global__ __launch_bounds__(256) void gemm_tf32_kernel(
    const float* __restrict__ A, const float* __restrict__ W,
    float* __restrict__ C, int M, int K, int Nc,
    const float* __restrict__ a_s, const float* __restrict__ a_d,
    float* __restrict__ as_out, float* __restrict__ ad_out, int H)
{
    extern __shared__ unsigned sm[];

    int tid = threadIdx.x;
    int bm = blockIdx.y * 128, bn = blockIdx.x * 64;
    int head = bn >> 6;
    int wid = tid >> 5, lane = tid & 31;
    int warpM = wid & 3, warpN = wid >> 2;       // 4 x 2
    int g = lane >> 2, t4 = lane & 3;

    float acc[2][4][4] = {};                     // [mfrag][nfrag][reg]

    int arow = tid >> 1;                 // 0..127
    int akc = (tid & 1) * 16;            // 0 or 16
    int brow = tid >> 3;                 // 0..31
    int bnc = (tid & 7) * 8;             // 0..56
    bool av = (bm + arow) < M;

    unsigned ua[16], ub[8];

    // -- prologue: load tile 0 --
    {
        const float* ap = A + (size_t)(bm + arow) * K + akc;
        #pragma unroll
        for (int i = 0; i < 4; i++) {
            float4 v = av ? *(const float4*)(ap + i * 4)
                          : make_float4(0.f, 0.f, 0.f, 0.f);
            ua[i * 4 + 0] = f2tf32(v.x); ua[i * 4 + 1] = f2tf32(v.y);
            ua[i * 4 + 2] = f2tf32(v.z); ua[i * 4 + 3] = f2tf32(v.w);
        }
        const float* wp = W + (size_t)brow * Nc + bn + bnc;
        #pragma unroll
        for (int i = 0; i < 2; i++) {
            float4 v = *(const float4*)(wp + i * 4);
            ub[i * 4 + 0] = f2tf32(v.x); ub[i * 4 + 1] = f2tf32(v.y);
            ub[i * 4 + 2] = f2tf32(v.z); ub[i * 4 + 3] = f2tf32(v.w);
        }
    }
    // store tile 0 into buffer 0
    {
        unsigned* Ap = sm;
        unsigned* Bp = sm + SM_BS_BASE;
        #pragma unroll
        for (int i = 0; i < 4; i++)
            *(uint4*)&Ap[arow * 36 + akc + i * 4] =
                make_uint4(ua[i*4+0], ua[i*4+1], ua[i*4+2], ua[i*4+3]);
        #pragma unroll
        for (int i = 0; i < 2; i++)
            *(uint4*)&Bp[brow * 68 + bnc + i * 4] =
                make_uint4(ub[i*4+0], ub[i*4+1], ub[i*4+2], ub[i*4+3]);
    }
    __syncthreads();

    int nt = K >> 5;
    for (int t = 0; t < nt; t++) {
        int cur = t & 1;
        bool more = (t + 1) < nt;

        // prefetch next tile into regs (overlaps with compute below)
        if (more) {
            int k0 = (t + 1) << 5;
            const float* ap = A + (size_t)(bm + arow) * K + k0 + akc;
            #pragma unroll
            for (int i = 0; i < 4; i++) {
                float4 v = av ? *(const float4*)(ap + i * 4)
                              : make_float4(0.f, 0.f, 0.f, 0.f);
                ua[i * 4 + 0] = f2tf32(v.x); ua[i * 4 + 1] = f2tf32(v.y);
                ua[i * 4 + 2] = f2tf32(v.z); ua[i * 4 + 3] = f2tf32(v.w);
            }
            const float* wp = W + (size_t)(k0 + brow) * Nc + bn + bnc;
            #pragma unroll
            for (int i = 0; i < 2; i++) {
                float4 v = *(const float4*)(wp + i * 4);
                ub[i * 4 + 0] = f2tf32(v.x); ub[i * 4 + 1] = f2tf32(v.y);
                ub[i * 4 + 2] = f2tf32(v.z); ub[i * 4 + 3] = f2tf32(v.w);
            }
        }

        // compute current buffer
        {
            const unsigned* Ap = sm + cur * AS_WORDS;
            const unsigned* Bp = sm + SM_BS_BASE + cur * BS_WORDS;
            #pragma unroll
            for (int ks = 0; ks < 4; ks++) {
                int kb = ks * 8;
                unsigned b0[4], b1[4];
                #pragma unroll
                for (int nf = 0; nf < 4; nf++) {
                    int nb = warpN * 32 + nf * 8 + g;
                    b0[nf] = Bp[(kb + t4) * 68 + nb];
                    b1[nf] = Bp[(kb + t4 + 4) * 68 + nb];
                }
                #pragma unroll
                for (int mf = 0; mf < 2; mf++) {
                    int rb = warpM * 32 + mf * 16;
                    unsigned a0 = Ap[(rb + g) * 36 + kb + t4];
                    unsigned a1 = Ap[(rb + g + 8) * 36 + kb + t4];
                    unsigned a2 = Ap[(rb + g) * 36 + kb + t4 + 4];
                    unsigned a3 = Ap[(rb + g + 8) * 36 + kb + t4 + 4];
                    #pragma unroll
                    for (int nf = 0; nf < 4; nf++) {
                        asm volatile(
                            "mma.sync.aligned.m16n8k8.row.col.f32.tf32.tf32.f32 "
                            "{%0,%1,%2,%3}, {%4,%5,%6,%7}, {%8,%9}, {%0,%1,%2,%3};"
                            : "+f"(acc[mf][nf][0]), "+f"(acc[mf][nf][1]),
                              "+f"(acc[mf][nf][2]), "+f"(acc[mf][nf][3])
                            : "r"(a0), "r"(a1), "r"(a2), "r"(a3),
                              "r"(b0[nf]), "r"(b1[nf]));
                    }
                }
            }
        }

        // store prefetched tile into the other buffer, then sync
        if (more) {
            unsigned* Ap = sm + (cur ^ 1) * AS_WORDS;
            unsigned* Bp = sm + SM_BS_BASE + (cur ^ 1) * BS_WORDS;
            #pragma unroll
            for (int i = 0; i < 4; i++)
                *(uint4*)&Ap[arow * 36 + akc + i * 4] =
                    make_uint4(ua[i*4+0], ua[i*4+1], ua[i*4+2], ua[i*4+3]);
            #pragma unroll
            for (int i = 0; i < 2; i++)
                *(uint4*)&Bp[brow * 68 + bnc + i * 4] =
                    make_uint4(ub[i*4+0], ub[i*4+1], ub[i*4+2], ub[i*4+3]);
            __syncthreads();
        }
    }

    // store C + fused alpha partials
    #pragma unroll
    for (int mf = 0; mf < 2; mf++) {
        int r0 = bm + warpM * 32 + mf * 16 + g;
        float s0 = 0.f, d0 = 0.f, s1 = 0.f, d1 = 0.f;  // rows r0, r0+8
        #pragma unroll
        for (int nf = 0; nf < 4; nf++) {
            int cc = warpN * 32 + nf * 8 + t4 * 2;   // in-head col (0..62)
            float w_s0 = a_s[head * 64 + cc],     w_s1 = a_s[head * 64 + cc + 1];
            float w_d0 = a_d[head * 64 + cc],     w_d1 = a_d[head * 64 + cc + 1];
            s0 += acc[mf][nf][0] * w_s0 + acc[mf][nf][1] * w_s1;
            d0 += acc[mf][nf][0] * w_d0 + acc[mf][nf][1] * w_d1;
            s1 += acc[mf][nf][2] * w_s0 + acc[mf][nf][3] * w_s1;
            d1 += acc[mf][nf][2] * w_d0 + acc[mf][nf][3] * w_d1;

            int col = bn + cc;
            if (r0 < M)
                *(float2*)(C + (size_t)r0 * Nc + col) =
                    make_float2(acc[mf][nf][0], acc[mf][nf][1]);
            if (r0 + 8 < M)
                *(float2*)(C + (size_t)(r0 + 8) * Nc + col) =
                    make_float2(acc[mf][nf][2], acc[mf][nf][3]);
        }
        // reduce across quad (same row, t4 = different col pairs)
        #pragma unroll
        for (int o = 1; o <= 2; o <<= 1) {
            s0 += __shfl_xor_sync(0xffffffffu, s0, o);
            d0 += __shfl_xor_sync(0xffffffffu, d0, o);
            s1 += __shfl_xor_sync(0xffffffffu, s1, o);
            d1 += __shfl_xor_sync(0xffffffffu, d1, o);
        }
        if (t4 == 0) {
            if (r0 < M) {
                atomicAdd(&as_out[r0 * H + head], s0);
                atomicAdd(&ad_out[r0 * H + head], d0);
            }
            if (r0 + 8 < M) {
                atomicAdd(&as_out[(r0 + 8) * H + head], s1);
                atomicAdd(&ad_out[(r0 + 8) * H + head], d1);
            }
        }
    }
}

// -------- aggregation: one warp per dst node, online-softmax CSR walk --------
template <int H>
__global__ __launch_bounds__(256) void aggregate_kernel(
    const float* __restrict__ as_, const float* __restrict__ ad_,
    const float* __restrict__ h,
    const float* __restrict__ b, float* __restrict__ outp, int relu)
{
    const int F = H * 64;
    const int VEC = F / 32;  // 8 (H=4) or 2 (H=1)
    int gtid = blockIdx.x * blockDim.x + threadIdx.x;
    int node = gtid >> 5;
    int lane = threadIdx.x & 31;
    if (node >= NN) return;
    int hh = (lane * VEC) >> 6;
    float adv = ad_[node * H + hh];
    int i0 = g_off[node], i1 = g_off[node + 1];

    float m = -1e30f, den = 0.f;
    float acc[VEC] = {};
    for (int i = i0; i < i1; i++) {
        int s = g_csrc[i];
        float x = as_[s * H + hh] + adv;
        x = x > 0.f ? x : 0.2f * x;
        if (x > m) {
            float r = __expf(m - x);
            den *= r;
            #pragma unroll
            for (int j = 0; j < VEC; j++) acc[j] *= r;
            m = x;
        }
        float ex = __expf(x - m);
        den += ex;
        const float* hp = h + (size_t)s * F + lane * VEC;
        if (VEC == 8) {
            float4 v0 = *(const float4*)hp;
            float4 v1 = *(const float4*)(hp + 4);
            acc[0] += ex * v0.x; acc[1] += ex * v0.y;
            acc[2] += ex * v0.z; acc[3] += ex * v0.w;
            acc[4] += ex * v1.x; acc[5] += ex * v1.y;
            acc[6] += ex * v1.z; acc[7] += ex * v1.w;
        } else {
            float2 v = *(const float2*)hp;
            acc[0] += ex * v.x; acc[1] += ex * v.y;
        }
    }
    float inv = 1.f / (den + 1e-16f);
    float* op = outp + (size_t)node * F + lane * VEC;
    #pragma unroll
    for (int j = 0; j < VEC; j++) {
        float v = acc[j] * inv + b[lane * VEC + j];
        if (relu) v = v > 0.f ? v : 0.f;
        op[j] = v;
    }
}

// -------- mean pool + head --------
__global__ void zero_pool_kernel(float* __restrict__ g) { g[threadIdx.x] = 0.f; }

__global__ void reduce_kernel(const float* __restrict__ h, float* __restrict__ g)
{
    int col = threadIdx.x & 63;
    float s = 0.f;
    for (int r = blockIdx.x * 4 + (threadIdx.x >> 6); r < NN; r += gridDim.x * 4)
        s += h[(size_t)r * 64 + col];
    atomicAdd(&g[col], s);
}

__global__ void head_kernel(const float* __restrict__ g, const float* __restrict__ hw,
                            const float* __restrict__ hb, float* __restrict__ out)
{
    int j = threadIdx.x;  // 64
    float s = 0.f;
    const float inv = 1.f / (float)NN;
    #pragma unroll 8
    for (int c = 0; c < 64; c++)
        s += (g[c] * inv) * hw[c * 64 + j];
    out[j] = s + hb[j];
}

extern "C" void kernel_launch(void* const* d_in, const int* in_sizes, int n_in,
                              void* d_out, int out_size)
{
    (void)in_sizes; (void)n_in; (void)out_size;
    const float* x   = (const float*)d_in[0];
    const int*   ei  = (const int*)d_in[1];
    const float* W0  = (const float*)d_in[2];
    const float* a0s = (const float*)d_in[3];
    const float* a0d = (const float*)d_in[4];
    const float* b0  = (const float*)d_in[5];
    const float* W1  = (const float*)d_in[6];
    const float* a1s = (const float*)d_in[7];
    const float* a1d = (const float*)d_in[8];
    const float* b1  = (const float*)d_in[9];
    const float* W2  = (const float*)d_in[10];
    const float* a2s = (const float*)d_in[11];
    const float* a2d = (const float*)d_in[12];
    const float* b2  = (const float*)d_in[13];
    const float* hw  = (const float*)d_in[14];
    const float* hb  = (const float*)d_in[15];
    float* out = (float*)d_out;

    float *bufA, *bufB, *as_, *ad_, *pool;
    cudaGetSymbolAddress((void**)&bufA, g_bufA);
    cudaGetSymbolAddress((void**)&bufB, g_bufB);
    cudaGetSymbolAddress((void**)&as_,  g_as);
    cudaGetSymbolAddress((void**)&ad_,  g_ad);
    cudaGetSymbolAddress((void**)&pool, g_pool);

    // >48KB dynamic smem opt-in (idempotent; not a stream op, graph-safe)
    cudaFuncSetAttribute(gemm_tf32_kernel,
                         cudaFuncAttributeMaxDynamicSharedMemorySize,
                         GEMM_SMEM_BYTES);

    // CSR prelude + layer-0 GEMM early so gemm0 lands in the profiled slot
    detect_kernel<<<1, 256>>>(ei);
    zero_cnt_alpha_kernel<<<(NN * 4 + 255) / 256, 256>>>();
    decode_kernel<<<(ENE + 255) / 256, 256>>>(ei);

    // Layer 0 GEMM: x[N,128] @ W0 -> bufA[N,256], fused alpha
    {
        dim3 grid(4, (NN + 127) / 128);
        gemm_tf32_kernel<<<grid, 256, GEMM_SMEM_BYTES>>>(
            x, W0, bufA, NN, 128, 256, a0s, a0d, as_, ad_, 4);
    }

    block_sum_kernel<<<SCAN_B, 256>>>();
    scan_bsum_kernel<<<1, 256>>>();
    scan_final_kernel<<<SCAN_B, 256>>>();
    scatter_kernel<<<(ENE + 255) / 256, 256>>>();

    aggregate_kernel<4><<<(NN * 32 + 255) / 256, 256>>>(as_, ad_, bufA, b0, bufB, 1);

    // Layer 1
    zero_alpha_kernel<<<(NN * 4 + 255) / 256, 256>>>(as_, ad_, NN * 4);
    {
        dim3 grid(4, (NN + 127) / 128);
        gemm_tf32_kernel<<<grid, 256, GEMM_SMEM_BYTES>>>(
            bufB, W1, bufA, NN, 256, 256, a1s, a1d, as_, ad_, 4);
    }
    aggregate_kernel<4><<<(NN * 32 + 255) / 256, 256>>>(as_, ad_, bufA, b1, bufB, 1);

    // Layer 2 (H=1)
    zero_alpha_kernel<<<(NN + 255) / 256, 256>>>(as_, ad_, NN);
    {
        dim3 grid(1, (NN + 127) / 128);
        gemm_tf32_kernel<<<grid, 256, GEMM_SMEM_BYTES>>>(
            bufB, W2, bufA, NN, 256, 64, a2s, a2d, as_, ad_, 1);
    }
    aggregate_kernel<1><<<(NN * 32 + 255) / 256, 256>>>(as_, ad_, bufA, b2, bufB, 0);

    zero_pool_kernel<<<1, 64>>>(pool);
    reduce_kernel<<<256, 256>>>(bufB, pool);
    head_kernel<<<1, 64>>>(pool, hw, hb, out);
}

// round 14
// speedup vs baseline: 1.0851x; 1.0851x over previous
#include <cuda_runtime.h>
#include <cstddef>

#define NN 50000
#define EE 800000
#define ENE (EE + NN)
#define SCAN_B 196   // ceil(NN/256)

// -------- scratch (static device globals; no allocation) --------
__device__ float g_bufA[NN * 256];   // GEMM output h per layer
__device__ float g_bufB[NN * 256];   // aggregation output / next-layer input
__device__ float g_as[NN * 4];
__device__ float g_ad[NN * 4];
__device__ float g_pool[64];
__device__ int g_is64;
__device__ int g_src[ENE];
__device__ int g_dst[ENE];
__device__ int g_cnt[NN];
__device__ int g_off[NN + 1];
__device__ int g_fill[NN];
__device__ int g_csrc[ENE];
__device__ int g_bsum[256];
__device__ int g_boff[256];

// -------- edge_index dtype detection --------
__global__ void detect_kernel(const int* __restrict__ ei32)
{
    __shared__ int sh[256];
    int acc = 0;
    for (int i = threadIdx.x; i < 65536; i += 256)
        acc |= ei32[2 * i + 1];
    sh[threadIdx.x] = acc;
    __syncthreads();
    for (int o = 128; o; o >>= 1) {
        if (threadIdx.x < o) sh[threadIdx.x] |= sh[threadIdx.x + o];
        __syncthreads();
    }
    if (threadIdx.x == 0) g_is64 = (sh[0] == 0) ? 1 : 0;
}

// -------- zero cnt + layer-0 alpha accumulators (one kernel) --------
__global__ void zero_cnt_alpha_kernel()
{
    int i = blockIdx.x * blockDim.x + threadIdx.x;
    if (i < NN) g_cnt[i] = 0;
    if (i < NN * 4) { g_as[i] = 0.f; g_ad[i] = 0.f; }
}

__global__ void zero_alpha_kernel(float* __restrict__ as_, float* __restrict__ ad_, int nh)
{
    int i = blockIdx.x * blockDim.x + threadIdx.x;
    if (i < nh) { as_[i] = 0.f; ad_[i] = 0.f; }
}

__global__ void decode_kernel(const int* __restrict__ ei32)
{
    int e = blockIdx.x * blockDim.x + threadIdx.x;
    if (e >= ENE) return;
    int s, d;
    if (e < EE) {
        if (g_is64) { s = ei32[2 * e]; d = ei32[2 * (EE + e)]; }
        else        { s = ei32[e];     d = ei32[EE + e]; }
        s = min(max(s, 0), NN - 1);
        d = min(max(d, 0), NN - 1);
    } else {
        s = d = e - EE;
    }
    g_src[e] = s;
    g_dst[e] = d;
    atomicAdd(&g_cnt[d], 1);
}

// 3-stage parallel exclusive scan of g_cnt -> g_off
__global__ void block_sum_kernel()
{
    __shared__ int sh[256];
    int t = threadIdx.x;
    int i = blockIdx.x * 256 + t;
    sh[t] = (i < NN) ? g_cnt[i] : 0;
    __syncthreads();
    for (int o = 128; o; o >>= 1) {
        if (t < o) sh[t] += sh[t + o];
        __syncthreads();
    }
    if (t == 0) g_bsum[blockIdx.x] = sh[0];
}

__global__ void scan_bsum_kernel()
{
    __shared__ int sh[256];
    int t = threadIdx.x;
    sh[t] = (t < SCAN_B) ? g_bsum[t] : 0;
    __syncthreads();
    for (int o = 1; o < 256; o <<= 1) {
        int u = (t >= o) ? sh[t - o] : 0;
        __syncthreads();
        sh[t] += u;
        __syncthreads();
    }
    g_boff[t] = t ? sh[t - 1] : 0;
    if (t == SCAN_B - 1) g_off[NN] = sh[t];
}

__global__ void scan_final_kernel()
{
    __shared__ int sh[256];
    int t = threadIdx.x;
    int i = blockIdx.x * 256 + t;
    int v = (i < NN) ? g_cnt[i] : 0;
    sh[t] = v;
    __syncthreads();
    for (int o = 1; o < 256; o <<= 1) {
        int u = (t >= o) ? sh[t - o] : 0;
        __syncthreads();
        sh[t] += u;
        __syncthreads();
    }
    if (i < NN) {
        int ex = sh[t] - v + g_boff[blockIdx.x];
        g_off[i] = ex;
        g_fill[i] = ex;
    }
}

__global__ void scatter_kernel()
{
    int e = blockIdx.x * blockDim.x + threadIdx.x;
    if (e >= ENE) return;
    int d = g_dst[e];
    int pos = atomicAdd(&g_fill[d], 1);
    g_csrc[pos] = g_src[e];
}

// -------- TF32 tensor-core GEMM + fused alpha epilogue --------
// C[M,Nc] = A[M,K] @ W[K,Nc]; BM=128, BN=NF*16, BK=32.
// 8 warps as 4(M) x 2(N); warp tile 32 x (NF*8); mma m16n8k8.
// NF=8: warp tile 32x64, 1.5 LDS/MMA; each warp maps to ONE head.
// NF=4: warp tile 32x32 (R11-proven shape) for Nc=64.
// Single-buffered smem, conflict-free scalar A-fragment loads.
__device__ __forceinline__ unsigned f2tf32(float f)
{
    unsigned u;
    asm("cvt.rna.tf32.f32 %0, %1;" : "=r"(u) : "f"(f));
    return u;
}

template <int NF>
__global__ __launch_bounds__(256) void gemm_tf32_kernel(
    const float* __restrict__ A, const float* __restrict__ W,
    float* __restrict__ C, int M, int K, int Nc,
    const float* __restrict__ a_s, const float* __restrict__ a_d,
    float* __restrict__ as_out, float* __restrict__ ad_out, int H)
{
    constexpr int BN = NF * 16;
    constexpr int TPR = BN / 8;          // threads per B row: 16 (NF8) / 8 (NF4)
    constexpr int RPP = 256 / TPR;       // rows per pass: 16 / 32
    constexpr int NPASS = 32 / RPP;      // passes: 2 / 1

    __shared__ unsigned As[128][36];     // [m][k] conflict-free fragment loads
    __shared__ unsigned Bs[32][BN + 4];  // [k][n]

    int tid = threadIdx.x;
    int bm = blockIdx.y * 128, bn = blockIdx.x * BN;
    int wid = tid >> 5, lane = tid & 31;
    int warpM = wid & 3, warpN = wid >> 2;       // 4 x 2
    int g = lane >> 2, t4 = lane & 3;
    int head = (bn + warpN * (NF * 8)) >> 6;     // one head per warp
    int chbase = (warpN * (NF * 8)) & 63;        // in-head col base

    float acc[2][NF][4] = {};                    // [mfrag][nfrag][reg]

    int arow = tid >> 1;                 // 0..127
    int akc = (tid & 1) * 16;            // 0 or 16
    int brow = tid / TPR;                // 0..RPP-1
    int bnc = (tid % TPR) * 8;
    bool av;

    for (int k0 = 0; k0 < K; k0 += 32) {
        av = (bm + arow) < M;
        const float* ap = A + (size_t)(bm + arow) * K + k0 + akc;
        #pragma unroll
        for (int i = 0; i < 4; i++) {
            float4 v = av ? *(const float4*)(ap + i * 4)
                          : make_float4(0.f, 0.f, 0.f, 0.f);
            As[arow][akc + i * 4 + 0] = f2tf32(v.x);
            As[arow][akc + i * 4 + 1] = f2tf32(v.y);
            As[arow][akc + i * 4 + 2] = f2tf32(v.z);
            As[arow][akc + i * 4 + 3] = f2tf32(v.w);
        }
        #pragma unroll
        for (int p = 0; p < NPASS; p++) {
            int br = brow + p * RPP;
            const float* wp = W + (size_t)(k0 + br) * Nc + bn + bnc;
            #pragma unroll
            for (int i = 0; i < 2; i++) {
                float4 v = *(const float4*)(wp + i * 4);
                Bs[br][bnc + i * 4 + 0] = f2tf32(v.x);
                Bs[br][bnc + i * 4 + 1] = f2tf32(v.y);
                Bs[br][bnc + i * 4 + 2] = f2tf32(v.z);
                Bs[br][bnc + i * 4 + 3] = f2tf32(v.w);
            }
        }
        __syncthreads();

        #pragma unroll
        for (int ks = 0; ks < 4; ks++) {
            int kb = ks * 8;
            unsigned b0[NF], b1[NF];
            #pragma unroll
            for (int nf = 0; nf < NF; nf++) {
                int nb = warpN * (NF * 8) + nf * 8 + g;
                b0[nf] = Bs[kb + t4][nb];
                b1[nf] = Bs[kb + t4 + 4][nb];
            }
            #pragma unroll
            for (int mf = 0; mf < 2; mf++) {
                int rb = warpM * 32 + mf * 16;
                unsigned a0 = As[rb + g][kb + t4];
                unsigned a1 = As[rb + g + 8][kb + t4];
                unsigned a2 = As[rb + g][kb + t4 + 4];
                unsigned a3 = As[rb + g + 8][kb + t4 + 4];
                #pragma unroll
                for (int nf = 0; nf < NF; nf++) {
                    asm volatile(
                        "mma.sync.aligned.m16n8k8.row.col.f32.tf32.tf32.f32 "
                        "{%0,%1,%2,%3}, {%4,%5,%6,%7}, {%8,%9}, {%0,%1,%2,%3};"
                        : "+f"(acc[mf][nf][0]), "+f"(acc[mf][nf][1]),
                          "+f"(acc[mf][nf][2]), "+f"(acc[mf][nf][3])
                        : "r"(a0), "r"(a1), "r"(a2), "r"(a3),
                          "r"(b0[nf]), "r"(b1[nf]));
                }
            }
        }
        __syncthreads();
    }

    // store C + fused alpha partials (one head per warp)
    #pragma unroll
    for (int mf = 0; mf < 2; mf++) {
        int r0 = bm + warpM * 32 + mf * 16 + g;
        float s0 = 0.f, d0 = 0.f, s1 = 0.f, d1 = 0.f;  // rows r0, r0+8
        #pragma unroll
        for (int nf = 0; nf < NF; nf++) {
            int cc = warpN * (NF * 8) + nf * 8 + t4 * 2;
            int ic = chbase + nf * 8 + t4 * 2;       // in-head col
            float w_s0 = a_s[head * 64 + ic],     w_s1 = a_s[head * 64 + ic + 1];
            float w_d0 = a_d[head * 64 + ic],     w_d1 = a_d[head * 64 + ic + 1];
            s0 += acc[mf][nf][0] * w_s0 + acc[mf][nf][1] * w_s1;
            d0 += acc[mf][nf][0] * w_d0 + acc[mf][nf][1] * w_d1;
            s1 += acc[mf][nf][2] * w_s0 + acc[mf][nf][3] * w_s1;
            d1 += acc[mf][nf][2] * w_d0 + acc[mf][nf][3] * w_d1;

            int col = bn + cc;
            if (r0 < M)
                *(float2*)(C + (size_t)r0 * Nc + col) =
                    make_float2(acc[mf][nf][0], acc[mf][nf][1]);
            if (r0 + 8 < M)
                *(float2*)(C + (size_t)(r0 + 8) * Nc + col) =
                    make_float2(acc[mf][nf][2], acc[mf][nf][3]);
        }
        // reduce across quad (same row, t4 = different col pairs)
        #pragma unroll
        for (int o = 1; o <= 2; o <<= 1) {
            s0 += __shfl_xor_sync(0xffffffffu, s0, o);
            d0 += __shfl_xor_sync(0xffffffffu, d0, o);
            s1 += __shfl_xor_sync(0xffffffffu, s1, o);
            d1 += __shfl_xor_sync(0xffffffffu, d1, o);
        }
        if (t4 == 0) {
            if (r0 < M) {
                atomicAdd(&as_out[r0 * H + head], s0);
                atomicAdd(&ad_out[r0 * H + head], d0);
            }
            if (r0 + 8 < M) {
                atomicAdd(&as_out[(r0 + 8) * H + head], s1);
                atomicAdd(&ad_out[(r0 + 8) * H + head], d1);
            }
        }
    }
}

// -------- aggregation: one warp per dst node, online-softmax CSR walk --------
template <int H>
__global__ __launch_bounds__(256) void aggregate_kernel(
    const float* __restrict__ as_, const float* __restrict__ ad_,
    const float* __restrict__ h,
    const float* __restrict__ b, float* __restrict__ outp, int relu)
{
    const int F = H * 64;
    const int VEC = F / 32;  // 8 (H=4) or 2 (H=1)
    int gtid = blockIdx.x * blockDim.x + threadIdx.x;
    int node = gtid >> 5;
    int lane = threadIdx.x & 31;
    if (node >= NN) return;
    int hh = (lane * VEC) >> 6;
    float adv = ad_[node * H + hh];
    int i0 = g_off[node], i1 = g_off[node + 1];

    float m = -1e30f, den = 0.f;
    float acc[VEC] = {};
    for (int i = i0; i < i1; i++) {
        int s = g_csrc[i];
        float x = as_[s * H + hh] + adv;
        x = x > 0.f ? x : 0.2f * x;
        if (x > m) {
            float r = __expf(m - x);
            den *= r;
            #pragma unroll
            for (int j = 0; j < VEC; j++) acc[j] *= r;
            m = x;
        }
        float ex = __expf(x - m);
        den += ex;
        const float* hp = h + (size_t)s * F + lane * VEC;
        if (VEC == 8) {
            float4 v0 = *(const float4*)hp;
            float4 v1 = *(const float4*)(hp + 4);
            acc[0] += ex * v0.x; acc[1] += ex * v0.y;
            acc[2] += ex * v0.z; acc[3] += ex * v0.w;
            acc[4] += ex * v1.x; acc[5] += ex * v1.y;
            acc[6] += ex * v1.z; acc[7] += ex * v1.w;
        } else {
            float2 v = *(const float2*)hp;
            acc[0] += ex * v.x; acc[1] += ex * v.y;
        }
    }
    float inv = 1.f / (den + 1e-16f);
    float* op = outp + (size_t)node * F + lane * VEC;
    #pragma unroll
    for (int j = 0; j < VEC; j++) {
        float v = acc[j] * inv + b[lane * VEC + j];
        if (relu) v = v > 0.f ? v : 0.f;
        op[j] = v;
    }
}

// -------- mean pool + head --------
__global__ void zero_pool_kernel(float* __restrict__ g) { g[threadIdx.x] = 0.f; }

__global__ void reduce_kernel(const float* __restrict__ h, float* __restrict__ g)
{
    int col = threadIdx.x & 63;
    float s = 0.f;
    for (int r = blockIdx.x * 4 + (threadIdx.x >> 6); r < NN; r += gridDim.x * 4)
        s += h[(size_t)r * 64 + col];
    atomicAdd(&g[col], s);
}

__global__ void head_kernel(const float* __restrict__ g, const float* __restrict__ hw,
                            const float* __restrict__ hb, float* __restrict__ out)
{
    int j = threadIdx.x;  // 64
    float s = 0.f;
    const float inv = 1.f / (float)NN;
    #pragma unroll 8
    for (int c = 0; c < 64; c++)
        s += (g[c] * inv) * hw[c * 64 + j];
    out[j] = s + hb[j];
}

extern "C" void kernel_launch(void* const* d_in, const int* in_sizes, int n_in,
                              void* d_out, int out_size)
{
    (void)in_sizes; (void)n_in; (void)out_size;
    const float* x   = (const float*)d_in[0];
    const int*   ei  = (const int*)d_in[1];
    const float* W0  = (const float*)d_in[2];
    const float* a0s = (const float*)d_in[3];
    const float* a0d = (const float*)d_in[4];
    const float* b0  = (const float*)d_in[5];
    const float* W1  = (const float*)d_in[6];
    const float* a1s = (const float*)d_in[7];
    const float* a1d = (const float*)d_in[8];
    const float* b1  = (const float*)d_in[9];
    const float* W2  = (const float*)d_in[10];
    const float* a2s = (const float*)d_in[11];
    const float* a2d = (const float*)d_in[12];
    const float* b2  = (const float*)d_in[13];
    const float* hw  = (const float*)d_in[14];
    const float* hb  = (const float*)d_in[15];
    float* out = (float*)d_out;

    float *bufA, *bufB, *as_, *ad_, *pool;
    cudaGetSymbolAddress((void**)&bufA, g_bufA);
    cudaGetSymbolAddress((void**)&bufB, g_bufB);
    cudaGetSymbolAddress((void**)&as_,  g_as);
    cudaGetSymbolAddress((void**)&ad_,  g_ad);
    cudaGetSymbolAddress((void**)&pool, g_pool);

    // CSR prelude + layer-0 GEMM early so gemm0 lands in the profiled slot
    detect_kernel<<<1, 256>>>(ei);
    zero_cnt_alpha_kernel<<<(NN * 4 + 255) / 256, 256>>>();
    decode_kernel<<<(ENE + 255) / 256, 256>>>(ei);

    // Layer 0 GEMM: x[N,128] @ W0 -> bufA[N,256], fused alpha (BN=128)
    {
        dim3 grid(2, (NN + 127) / 128);
        gemm_tf32_kernel<8><<<grid, 256>>>(x, W0, bufA, NN, 128, 256, a0s, a0d, as_, ad_, 4);
    }

    block_sum_kernel<<<SCAN_B, 256>>>();
    scan_bsum_kernel<<<1, 256>>>();
    scan_final_kernel<<<SCAN_B, 256>>>();
    scatter_kernel<<<(ENE + 255) / 256, 256>>>();

    aggregate_kernel<4><<<(NN * 32 + 255) / 256, 256>>>(as_, ad_, bufA, b0, bufB, 1);

    // Layer 1
    zero_alpha_kernel<<<(NN * 4 + 255) / 256, 256>>>(as_, ad_, NN * 4);
    {
        dim3 grid(2, (NN + 127) / 128);
        gemm_tf32_kernel<8><<<grid, 256>>>(bufB, W1, bufA, NN, 256, 256, a1s, a1d, as_, ad_, 4);
    }
    aggregate_kernel<4><<<(NN * 32 + 255) / 256, 256>>>(as_, ad_, bufA, b1, bufB, 1);

    // Layer 2 (H=1, Nc=64 -> NF=4 shape)
    zero_alpha_kernel<<<(NN + 255) / 256, 256>>>(as_, ad_, NN);
    {
        dim3 grid(1, (NN + 127) / 128);
        gemm_tf32_kernel<4><<<grid, 256>>>(bufB, W2, bufA, NN, 256, 64, a2s, a2d, as_, ad_, 1);
    }
    aggregate_kernel<1><<<(NN * 32 + 255) / 256, 256>>>(as_, ad_, bufA, b2, bufB, 0);

    zero_pool_kernel<<<1, 64>>>(pool);
    reduce_kernel<<<256, 256>>>(bufB, pool);
    head_kernel<<<1, 64>>>(pool, hw, hb, out);
}

// round 15
// speedup vs baseline: 1.2323x; 1.1356x over previous
#include <cuda_runtime.h>
#include <cuda_fp16.h>
#include <cstddef>

#define NN 50000
#define EE 800000
#define ENE (EE + NN)
#define SCAN_B 196   // ceil(NN/256)

// -------- scratch (static device globals; no allocation) --------
__device__ __half g_hb[NN * 256];    // GEMM output h per layer (fp16 gather buffer)
__device__ float g_bufB[NN * 256];   // aggregation output / next-layer input (fp32)
__device__ float g_as[NN * 4];
__device__ float g_ad[NN * 4];
__device__ float g_pool[64];
__device__ int g_is64;
__device__ int g_src[ENE];
__device__ int g_dst[ENE];
__device__ int g_cnt[NN];
__device__ int g_off[NN + 1];
__device__ int g_fill[NN];
__device__ int g_csrc[ENE];
__device__ int g_bsum[256];
__device__ int g_boff[256];

// -------- edge_index dtype detection --------
__global__ void detect_kernel(const int* __restrict__ ei32)
{
    __shared__ int sh[256];
    int acc = 0;
    for (int i = threadIdx.x; i < 65536; i += 256)
        acc |= ei32[2 * i + 1];
    sh[threadIdx.x] = acc;
    __syncthreads();
    for (int o = 128; o; o >>= 1) {
        if (threadIdx.x < o) sh[threadIdx.x] |= sh[threadIdx.x + o];
        __syncthreads();
    }
    if (threadIdx.x == 0) g_is64 = (sh[0] == 0) ? 1 : 0;
}

// -------- zero cnt + layer-0 alpha accumulators (one kernel) --------
__global__ void zero_cnt_alpha_kernel()
{
    int i = blockIdx.x * blockDim.x + threadIdx.x;
    if (i < NN) g_cnt[i] = 0;
    if (i < NN * 4) { g_as[i] = 0.f; g_ad[i] = 0.f; }
}

__global__ void zero_alpha_kernel(float* __restrict__ as_, float* __restrict__ ad_, int nh)
{
    int i = blockIdx.x * blockDim.x + threadIdx.x;
    if (i < nh) { as_[i] = 0.f; ad_[i] = 0.f; }
}

__global__ void decode_kernel(const int* __restrict__ ei32)
{
    int e = blockIdx.x * blockDim.x + threadIdx.x;
    if (e >= ENE) return;
    int s, d;
    if (e < EE) {
        if (g_is64) { s = ei32[2 * e]; d = ei32[2 * (EE + e)]; }
        else        { s = ei32[e];     d = ei32[EE + e]; }
        s = min(max(s, 0), NN - 1);
        d = min(max(d, 0), NN - 1);
    } else {
        s = d = e - EE;
    }
    g_src[e] = s;
    g_dst[e] = d;
    atomicAdd(&g_cnt[d], 1);
}

// 3-stage parallel exclusive scan of g_cnt -> g_off
__global__ void block_sum_kernel()
{
    __shared__ int sh[256];
    int t = threadIdx.x;
    int i = blockIdx.x * 256 + t;
    sh[t] = (i < NN) ? g_cnt[i] : 0;
    __syncthreads();
    for (int o = 128; o; o >>= 1) {
        if (t < o) sh[t] += sh[t + o];
        __syncthreads();
    }
    if (t == 0) g_bsum[blockIdx.x] = sh[0];
}

__global__ void scan_bsum_kernel()
{
    __shared__ int sh[256];
    int t = threadIdx.x;
    sh[t] = (t < SCAN_B) ? g_bsum[t] : 0;
    __syncthreads();
    for (int o = 1; o < 256; o <<= 1) {
        int u = (t >= o) ? sh[t - o] : 0;
        __syncthreads();
        sh[t] += u;
        __syncthreads();
    }
    g_boff[t] = t ? sh[t - 1] : 0;
    if (t == SCAN_B - 1) g_off[NN] = sh[t];
}

__global__ void scan_final_kernel()
{
    __shared__ int sh[256];
    int t = threadIdx.x;
    int i = blockIdx.x * 256 + t;
    int v = (i < NN) ? g_cnt[i] : 0;
    sh[t] = v;
    __syncthreads();
    for (int o = 1; o < 256; o <<= 1) {
        int u = (t >= o) ? sh[t - o] : 0;
        __syncthreads();
        sh[t] += u;
        __syncthreads();
    }
    if (i < NN) {
        int ex = sh[t] - v + g_boff[blockIdx.x];
        g_off[i] = ex;
        g_fill[i] = ex;
    }
}

__global__ void scatter_kernel()
{
    int e = blockIdx.x * blockDim.x + threadIdx.x;
    if (e >= ENE) return;
    int d = g_dst[e];
    int pos = atomicAdd(&g_fill[d], 1);
    g_csrc[pos] = g_src[e];
}

// -------- TF32 tensor-core GEMM + fused alpha epilogue, fp16 C output --------
// C[M,Nc] = A[M,K] @ W[K,Nc]; BM=128, BN=NF*16, BK=32.
// 8 warps as 4(M) x 2(N); warp tile 32 x (NF*8); mma m16n8k8.
// NF=8: warp tile 32x64, each warp maps to ONE head. NF=4 for Nc=64.
// C stored as __half (halves gather traffic downstream); alpha from fp32 acc.
__device__ __forceinline__ unsigned f2tf32(float f)
{
    unsigned u;
    asm("cvt.rna.tf32.f32 %0, %1;" : "=r"(u) : "f"(f));
    return u;
}

template <int NF>
__global__ __launch_bounds__(256) void gemm_tf32_kernel(
    const float* __restrict__ A, const float* __restrict__ W,
    __half* __restrict__ C, int M, int K, int Nc,
    const float* __restrict__ a_s, const float* __restrict__ a_d,
    float* __restrict__ as_out, float* __restrict__ ad_out, int H)
{
    constexpr int BN = NF * 16;
    constexpr int TPR = BN / 8;          // threads per B row
    constexpr int RPP = 256 / TPR;       // rows per pass
    constexpr int NPASS = 32 / RPP;

    __shared__ unsigned As[128][36];     // [m][k] conflict-free fragment loads
    __shared__ unsigned Bs[32][BN + 4];  // [k][n]

    int tid = threadIdx.x;
    int bm = blockIdx.y * 128, bn = blockIdx.x * BN;
    int wid = tid >> 5, lane = tid & 31;
    int warpM = wid & 3, warpN = wid >> 2;       // 4 x 2
    int g = lane >> 2, t4 = lane & 3;
    int head = (bn + warpN * (NF * 8)) >> 6;     // one head per warp
    int chbase = (warpN * (NF * 8)) & 63;

    float acc[2][NF][4] = {};

    int arow = tid >> 1;
    int akc = (tid & 1) * 16;
    int brow = tid / TPR;
    int bnc = (tid % TPR) * 8;
    bool av;

    for (int k0 = 0; k0 < K; k0 += 32) {
        av = (bm + arow) < M;
        const float* ap = A + (size_t)(bm + arow) * K + k0 + akc;
        #pragma unroll
        for (int i = 0; i < 4; i++) {
            float4 v = av ? *(const float4*)(ap + i * 4)
                          : make_float4(0.f, 0.f, 0.f, 0.f);
            As[arow][akc + i * 4 + 0] = f2tf32(v.x);
            As[arow][akc + i * 4 + 1] = f2tf32(v.y);
            As[arow][akc + i * 4 + 2] = f2tf32(v.z);
            As[arow][akc + i * 4 + 3] = f2tf32(v.w);
        }
        #pragma unroll
        for (int p = 0; p < NPASS; p++) {
            int br = brow + p * RPP;
            const float* wp = W + (size_t)(k0 + br) * Nc + bn + bnc;
            #pragma unroll
            for (int i = 0; i < 2; i++) {
                float4 v = *(const float4*)(wp + i * 4);
                Bs[br][bnc + i * 4 + 0] = f2tf32(v.x);
                Bs[br][bnc + i * 4 + 1] = f2tf32(v.y);
                Bs[br][bnc + i * 4 + 2] = f2tf32(v.z);
                Bs[br][bnc + i * 4 + 3] = f2tf32(v.w);
            }
        }
        __syncthreads();

        #pragma unroll
        for (int ks = 0; ks < 4; ks++) {
            int kb = ks * 8;
            unsigned b0[NF], b1[NF];
            #pragma unroll
            for (int nf = 0; nf < NF; nf++) {
                int nb = warpN * (NF * 8) + nf * 8 + g;
                b0[nf] = Bs[kb + t4][nb];
                b1[nf] = Bs[kb + t4 + 4][nb];
            }
            #pragma unroll
            for (int mf = 0; mf < 2; mf++) {
                int rb = warpM * 32 + mf * 16;
                unsigned a0 = As[rb + g][kb + t4];
                unsigned a1 = As[rb + g + 8][kb + t4];
                unsigned a2 = As[rb + g][kb + t4 + 4];
                unsigned a3 = As[rb + g + 8][kb + t4 + 4];
                #pragma unroll
                for (int nf = 0; nf < NF; nf++) {
                    asm volatile(
                        "mma.sync.aligned.m16n8k8.row.col.f32.tf32.tf32.f32 "
                        "{%0,%1,%2,%3}, {%4,%5,%6,%7}, {%8,%9}, {%0,%1,%2,%3};"
                        : "+f"(acc[mf][nf][0]), "+f"(acc[mf][nf][1]),
                          "+f"(acc[mf][nf][2]), "+f"(acc[mf][nf][3])
                        : "r"(a0), "r"(a1), "r"(a2), "r"(a3),
                          "r"(b0[nf]), "r"(b1[nf]));
                }
            }
        }
        __syncthreads();
    }

    // store C (fp16) + fused alpha partials (fp32 acc; one head per warp)
    #pragma unroll
    for (int mf = 0; mf < 2; mf++) {
        int r0 = bm + warpM * 32 + mf * 16 + g;
        float s0 = 0.f, d0 = 0.f, s1 = 0.f, d1 = 0.f;  // rows r0, r0+8
        #pragma unroll
        for (int nf = 0; nf < NF; nf++) {
            int cc = warpN * (NF * 8) + nf * 8 + t4 * 2;
            int ic = chbase + nf * 8 + t4 * 2;
            float w_s0 = a_s[head * 64 + ic],     w_s1 = a_s[head * 64 + ic + 1];
            float w_d0 = a_d[head * 64 + ic],     w_d1 = a_d[head * 64 + ic + 1];
            s0 += acc[mf][nf][0] * w_s0 + acc[mf][nf][1] * w_s1;
            d0 += acc[mf][nf][0] * w_d0 + acc[mf][nf][1] * w_d1;
            s1 += acc[mf][nf][2] * w_s0 + acc[mf][nf][3] * w_s1;
            d1 += acc[mf][nf][2] * w_d0 + acc[mf][nf][3] * w_d1;

            int col = bn + cc;
            if (r0 < M)
                *(__half2*)(C + (size_t)r0 * Nc + col) =
                    __floats2half2_rn(acc[mf][nf][0], acc[mf][nf][1]);
            if (r0 + 8 < M)
                *(__half2*)(C + (size_t)(r0 + 8) * Nc + col) =
                    __floats2half2_rn(acc[mf][nf][2], acc[mf][nf][3]);
        }
        #pragma unroll
        for (int o = 1; o <= 2; o <<= 1) {
            s0 += __shfl_xor_sync(0xffffffffu, s0, o);
            d0 += __shfl_xor_sync(0xffffffffu, d0, o);
            s1 += __shfl_xor_sync(0xffffffffu, s1, o);
            d1 += __shfl_xor_sync(0xffffffffu, d1, o);
        }
        if (t4 == 0) {
            if (r0 < M) {
                atomicAdd(&as_out[r0 * H + head], s0);
                atomicAdd(&ad_out[r0 * H + head], d0);
            }
            if (r0 + 8 < M) {
                atomicAdd(&as_out[(r0 + 8) * H + head], s1);
                atomicAdd(&ad_out[(r0 + 8) * H + head], d1);
            }
        }
    }
}

// -------- aggregation: one warp per dst node, online-softmax CSR walk --------
// h gathered in fp16 (16 B per lane per edge, H=4); fp32 accumulate + output.
template <int H>
__global__ __launch_bounds__(256) void aggregate_kernel(
    const float* __restrict__ as_, const float* __restrict__ ad_,
    const __half* __restrict__ h,
    const float* __restrict__ b, float* __restrict__ outp, int relu)
{
    const int F = H * 64;
    const int VEC = F / 32;  // 8 (H=4) or 2 (H=1)
    int gtid = blockIdx.x * blockDim.x + threadIdx.x;
    int node = gtid >> 5;
    int lane = threadIdx.x & 31;
    if (node >= NN) return;
    int hh = (lane * VEC) >> 6;
    float adv = ad_[node * H + hh];
    int i0 = g_off[node], i1 = g_off[node + 1];

    float m = -1e30f, den = 0.f;
    float acc[VEC] = {};
    for (int i = i0; i < i1; i++) {
        int s = g_csrc[i];
        float x = as_[s * H + hh] + adv;
        x = x > 0.f ? x : 0.2f * x;
        if (x > m) {
            float r = __expf(m - x);
            den *= r;
            #pragma unroll
            for (int j = 0; j < VEC; j++) acc[j] *= r;
            m = x;
        }
        float ex = __expf(x - m);
        den += ex;
        const __half* hp = h + (size_t)s * F + lane * VEC;
        if (VEC == 8) {
            uint4 u = *(const uint4*)hp;
            float2 f0 = __half22float2(*(__half2*)&u.x);
            float2 f1 = __half22float2(*(__half2*)&u.y);
            float2 f2 = __half22float2(*(__half2*)&u.z);
            float2 f3 = __half22float2(*(__half2*)&u.w);
            acc[0] += ex * f0.x; acc[1] += ex * f0.y;
            acc[2] += ex * f1.x; acc[3] += ex * f1.y;
            acc[4] += ex * f2.x; acc[5] += ex * f2.y;
            acc[6] += ex * f3.x; acc[7] += ex * f3.y;
        } else {
            unsigned u = *(const unsigned*)hp;
            float2 f = __half22float2(*(__half2*)&u);
            acc[0] += ex * f.x; acc[1] += ex * f.y;
        }
    }
    float inv = 1.f / (den + 1e-16f);
    float* op = outp + (size_t)node * F + lane * VEC;
    #pragma unroll
    for (int j = 0; j < VEC; j++) {
        float v = acc[j] * inv + b[lane * VEC + j];
        if (relu) v = v > 0.f ? v : 0.f;
        op[j] = v;
    }
}

// -------- mean pool + head --------
__global__ void zero_pool_kernel(float* __restrict__ g) { g[threadIdx.x] = 0.f; }

__global__ void reduce_kernel(const float* __restrict__ h, float* __restrict__ g)
{
    int col = threadIdx.x & 63;
    float s = 0.f;
    for (int r = blockIdx.x * 4 + (threadIdx.x >> 6); r < NN; r += gridDim.x * 4)
        s += h[(size_t)r * 64 + col];
    atomicAdd(&g[col], s);
}

__global__ void head_kernel(const float* __restrict__ g, const float* __restrict__ hw,
                            const float* __restrict__ hb, float* __restrict__ out)
{
    int j = threadIdx.x;  // 64
    float s = 0.f;
    const float inv = 1.f / (float)NN;
    #pragma unroll 8
    for (int c = 0; c < 64; c++)
        s += (g[c] * inv) * hw[c * 64 + j];
    out[j] = s + hb[j];
}

extern "C" void kernel_launch(void* const* d_in, const int* in_sizes, int n_in,
                              void* d_out, int out_size)
{
    (void)in_sizes; (void)n_in; (void)out_size;
    const float* x   = (const float*)d_in[0];
    const int*   ei  = (const int*)d_in[1];
    const float* W0  = (const float*)d_in[2];
    const float* a0s = (const float*)d_in[3];
    const float* a0d = (const float*)d_in[4];
    const float* b0  = (const float*)d_in[5];
    const float* W1  = (const float*)d_in[6];
    const float* a1s = (const float*)d_in[7];
    const float* a1d = (const float*)d_in[8];
    const float* b1  = (const float*)d_in[9];
    const float* W2  = (const float*)d_in[10];
    const float* a2s = (const float*)d_in[11];
    const float* a2d = (const float*)d_in[12];
    const float* b2  = (const float*)d_in[13];
    const float* hw  = (const float*)d_in[14];
    const float* hb  = (const float*)d_in[15];
    float* out = (float*)d_out;

    __half* hbuf;
    float *bufB, *as_, *ad_, *pool;
    cudaGetSymbolAddress((void**)&hbuf, g_hb);
    cudaGetSymbolAddress((void**)&bufB, g_bufB);
    cudaGetSymbolAddress((void**)&as_,  g_as);
    cudaGetSymbolAddress((void**)&ad_,  g_ad);
    cudaGetSymbolAddress((void**)&pool, g_pool);

    // CSR prelude + layer-0 GEMM early so gemm0 lands in the profiled slot
    detect_kernel<<<1, 256>>>(ei);
    zero_cnt_alpha_kernel<<<(NN * 4 + 255) / 256, 256>>>();
    decode_kernel<<<(ENE + 255) / 256, 256>>>(ei);

    // Layer 0 GEMM: x[N,128] @ W0 -> hbuf[N,256] fp16, fused alpha (BN=128)
    {
        dim3 grid(2, (NN + 127) / 128);
        gemm_tf32_kernel<8><<<grid, 256>>>(x, W0, hbuf, NN, 128, 256, a0s, a0d, as_, ad_, 4);
    }

    block_sum_kernel<<<SCAN_B, 256>>>();
    scan_bsum_kernel<<<1, 256>>>();
    scan_final_kernel<<<SCAN_B, 256>>>();
    scatter_kernel<<<(ENE + 255) / 256, 256>>>();

    aggregate_kernel<4><<<(NN * 32 + 255) / 256, 256>>>(as_, ad_, hbuf, b0, bufB, 1);

    // Layer 1
    zero_alpha_kernel<<<(NN * 4 + 255) / 256, 256>>>(as_, ad_, NN * 4);
    {
        dim3 grid(2, (NN + 127) / 128);
        gemm_tf32_kernel<8><<<grid, 256>>>(bufB, W1, hbuf, NN, 256, 256, a1s, a1d, as_, ad_, 4);
    }
    aggregate_kernel<4><<<(NN * 32 + 255) / 256, 256>>>(as_, ad_, hbuf, b1, bufB, 1);

    // Layer 2 (H=1, Nc=64 -> NF=4 shape)
    zero_alpha_kernel<<<(NN + 255) / 256, 256>>>(as_, ad_, NN);
    {
        dim3 grid(1, (NN + 127) / 128);
        gemm_tf32_kernel<4><<<grid, 256>>>(bufB, W2, hbuf, NN, 256, 64, a2s, a2d, as_, ad_, 1);
    }
    aggregate_kernel<1><<<(NN * 32 + 255) / 256, 256>>>(as_, ad_, hbuf, b2, bufB, 0);

    zero_pool_kernel<<<1, 64>>>(pool);
    reduce_kernel<<<256, 256>>>(bufB, pool);
    head_kernel<<<1, 64>>>(pool, hw, hb, out);
}

// round 16
// speedup vs baseline: 1.4010x; 1.1369x over previous
#include <cuda_runtime.h>
#include <cuda_fp16.h>
#include <cstddef>

#define NN 50000
#define EE 800000
#define ENE (EE + NN)
#define SCAN_B 196   // ceil(NN/256)

// -------- scratch (static device globals; no allocation) --------
__device__ __half g_hb[NN * 256];    // GEMM output h per layer (fp16 gather buffer)
__device__ float g_bufB[NN * 256];   // aggregation output / next-layer input (fp32)
__device__ float g_as[NN * 4];
__device__ float g_ad[NN * 4];
__device__ float g_pool[64];
__device__ int g_is64;
__device__ int g_src[ENE];
__device__ int g_dst[ENE];
__device__ int g_cnt[NN];
__device__ int g_off[NN + 1];
__device__ int g_fill[NN];
__device__ int g_csrc[ENE];
__device__ int g_bsum[256];
__device__ int g_boff[256];

// -------- edge_index dtype detection --------
__global__ void detect_kernel(const int* __restrict__ ei32)
{
    __shared__ int sh[256];
    int acc = 0;
    for (int i = threadIdx.x; i < 65536; i += 256)
        acc |= ei32[2 * i + 1];
    sh[threadIdx.x] = acc;
    __syncthreads();
    for (int o = 128; o; o >>= 1) {
        if (threadIdx.x < o) sh[threadIdx.x] |= sh[threadIdx.x + o];
        __syncthreads();
    }
    if (threadIdx.x == 0) g_is64 = (sh[0] == 0) ? 1 : 0;
}

// -------- zero cnt + layer-0 alpha accumulators (one kernel) --------
__global__ void zero_cnt_alpha_kernel()
{
    int i = blockIdx.x * blockDim.x + threadIdx.x;
    if (i < NN) g_cnt[i] = 0;
    if (i < NN * 4) { g_as[i] = 0.f; g_ad[i] = 0.f; }
}

__global__ void zero_alpha_kernel(float* __restrict__ as_, float* __restrict__ ad_, int nh)
{
    int i = blockIdx.x * blockDim.x + threadIdx.x;
    if (i < nh) { as_[i] = 0.f; ad_[i] = 0.f; }
}

__global__ void decode_kernel(const int* __restrict__ ei32)
{
    int e = blockIdx.x * blockDim.x + threadIdx.x;
    if (e >= ENE) return;
    int s, d;
    if (e < EE) {
        if (g_is64) { s = ei32[2 * e]; d = ei32[2 * (EE + e)]; }
        else        { s = ei32[e];     d = ei32[EE + e]; }
        s = min(max(s, 0), NN - 1);
        d = min(max(d, 0), NN - 1);
    } else {
        s = d = e - EE;
    }
    g_src[e] = s;
    g_dst[e] = d;
    atomicAdd(&g_cnt[d], 1);
}

// 3-stage parallel exclusive scan of g_cnt -> g_off
__global__ void block_sum_kernel()
{
    __shared__ int sh[256];
    int t = threadIdx.x;
    int i = blockIdx.x * 256 + t;
    sh[t] = (i < NN) ? g_cnt[i] : 0;
    __syncthreads();
    for (int o = 128; o; o >>= 1) {
        if (t < o) sh[t] += sh[t + o];
        __syncthreads();
    }
    if (t == 0) g_bsum[blockIdx.x] = sh[0];
}

__global__ void scan_bsum_kernel()
{
    __shared__ int sh[256];
    int t = threadIdx.x;
    sh[t] = (t < SCAN_B) ? g_bsum[t] : 0;
    __syncthreads();
    for (int o = 1; o < 256; o <<= 1) {
        int u = (t >= o) ? sh[t - o] : 0;
        __syncthreads();
        sh[t] += u;
        __syncthreads();
    }
    g_boff[t] = t ? sh[t - 1] : 0;
    if (t == SCAN_B - 1) g_off[NN] = sh[t];
}

__global__ void scan_final_kernel()
{
    __shared__ int sh[256];
    int t = threadIdx.x;
    int i = blockIdx.x * 256 + t;
    int v = (i < NN) ? g_cnt[i] : 0;
    sh[t] = v;
    __syncthreads();
    for (int o = 1; o < 256; o <<= 1) {
        int u = (t >= o) ? sh[t - o] : 0;
        __syncthreads();
        sh[t] += u;
        __syncthreads();
    }
    if (i < NN) {
        int ex = sh[t] - v + g_boff[blockIdx.x];
        g_off[i] = ex;
        g_fill[i] = ex;
    }
}

__global__ void scatter_kernel()
{
    int e = blockIdx.x * blockDim.x + threadIdx.x;
    if (e >= ENE) return;
    int d = g_dst[e];
    int pos = atomicAdd(&g_fill[d], 1);
    g_csrc[pos] = g_src[e];
}

// -------- FP16 tensor-core GEMM (fp32 accumulate) + fused alpha epilogue --------
// C[M,Nc] = A[M,K] @ W[K,Nc]; BM=128, BN=NF*16, BK=32; mma m16n8k16.f32.f16.f16.f32.
// 8 warps as 4(M) x 2(N); warp tile 32 x (NF*8). NF=8 (one head per warp) / NF=4.
// Smem holds half2 words. A: [128][20] (16 k-pairs + pad4) -> fragment banks 20g+t4
// all-distinct. B pair-major [16][BN+8]: stride ≡ 8 (mod 32) -> banks 8*t4+g distinct.
__device__ __forceinline__ unsigned pack_h2(float lo, float hi)
{
    __half2 h = __floats2half2_rn(lo, hi);
    return *(unsigned*)&h;
}

template <int NF>
__global__ __launch_bounds__(256) void gemm_f16_kernel(
    const float* __restrict__ A, const float* __restrict__ W,
    __half* __restrict__ C, int M, int K, int Nc,
    const float* __restrict__ a_s, const float* __restrict__ a_d,
    float* __restrict__ as_out, float* __restrict__ ad_out, int H)
{
    constexpr int BN = NF * 16;
    constexpr int BSTRIDE = BN + 8;      // half2 words per B pair-row (≡8 mod 32)

    __shared__ unsigned As2[128][20];    // [m][k-pair]
    __shared__ unsigned Bs2[16][BSTRIDE];// [k-pair][n]

    int tid = threadIdx.x;
    int bm = blockIdx.y * 128, bn = blockIdx.x * BN;
    int wid = tid >> 5, lane = tid & 31;
    int warpM = wid & 3, warpN = wid >> 2;       // 4 x 2
    int g = lane >> 2, t4 = lane & 3;
    int head = (bn + warpN * (NF * 8)) >> 6;     // one head per warp
    int chbase = (warpN * (NF * 8)) & 63;

    float acc[2][NF][4] = {};

    int arow = tid >> 1;                 // 0..127
    int akc = (tid & 1) * 16;            // k offset 0 or 16
    // B staging: pair p, col-group cg (8 cols each)
    int bp, bcg;
    bool bact;
    if (NF == 8) { bp = tid >> 4; bcg = tid & 15; bact = true; }
    else         { bp = tid >> 3; bcg = tid & 7;  bact = (tid < 128); }

    for (int k0 = 0; k0 < K; k0 += 32) {
        // A tile: 16 fp32 -> 8 half2 words
        {
            bool av = (bm + arow) < M;
            const float* ap = A + (size_t)(bm + arow) * K + k0 + akc;
            unsigned w[8];
            #pragma unroll
            for (int i = 0; i < 4; i++) {
                float4 v = av ? *(const float4*)(ap + i * 4)
                              : make_float4(0.f, 0.f, 0.f, 0.f);
                w[i * 2 + 0] = pack_h2(v.x, v.y);
                w[i * 2 + 1] = pack_h2(v.z, v.w);
            }
            unsigned* dst = &As2[arow][akc >> 1];
            *(uint4*)(dst + 0) = make_uint4(w[0], w[1], w[2], w[3]);
            *(uint4*)(dst + 4) = make_uint4(w[4], w[5], w[6], w[7]);
        }
        // B tile: rows k0+2p, k0+2p+1, cols bn+cg*8..+7 -> 8 half2 words
        if (bact) {
            const float* w0 = W + (size_t)(k0 + 2 * bp) * Nc + bn + bcg * 8;
            const float* w1 = w0 + Nc;
            float4 r0a = *(const float4*)w0,      r1a = *(const float4*)w1;
            float4 r0b = *(const float4*)(w0+4),  r1b = *(const float4*)(w1+4);
            unsigned* dst = &Bs2[bp][bcg * 8];
            *(uint4*)(dst + 0) = make_uint4(
                pack_h2(r0a.x, r1a.x), pack_h2(r0a.y, r1a.y),
                pack_h2(r0a.z, r1a.z), pack_h2(r0a.w, r1a.w));
            *(uint4*)(dst + 4) = make_uint4(
                pack_h2(r0b.x, r1b.x), pack_h2(r0b.y, r1b.y),
                pack_h2(r0b.z, r1b.z), pack_h2(r0b.w, r1b.w));
        }
        __syncthreads();

        #pragma unroll
        for (int ks = 0; ks < 2; ks++) {            // two k16 steps per 32-k tile
            int pb = ks * 8;                        // pair base
            unsigned b0[NF], b1[NF];
            #pragma unroll
            for (int nf = 0; nf < NF; nf++) {
                int nb = warpN * (NF * 8) + nf * 8 + g;
                b0[nf] = Bs2[pb + t4][nb];
                b1[nf] = Bs2[pb + t4 + 4][nb];
            }
            #pragma unroll
            for (int mf = 0; mf < 2; mf++) {
                int rb = warpM * 32 + mf * 16;
                unsigned a0 = As2[rb + g][pb + t4];
                unsigned a1 = As2[rb + g + 8][pb + t4];
                unsigned a2 = As2[rb + g][pb + t4 + 4];
                unsigned a3 = As2[rb + g + 8][pb + t4 + 4];
                #pragma unroll
                for (int nf = 0; nf < NF; nf++) {
                    asm volatile(
                        "mma.sync.aligned.m16n8k16.row.col.f32.f16.f16.f32 "
                        "{%0,%1,%2,%3}, {%4,%5,%6,%7}, {%8,%9}, {%0,%1,%2,%3};"
                        : "+f"(acc[mf][nf][0]), "+f"(acc[mf][nf][1]),
                          "+f"(acc[mf][nf][2]), "+f"(acc[mf][nf][3])
                        : "r"(a0), "r"(a1), "r"(a2), "r"(a3),
                          "r"(b0[nf]), "r"(b1[nf]));
                }
            }
        }
        __syncthreads();
    }

    // store C (fp16) + fused alpha partials (fp32 acc; one head per warp)
    #pragma unroll
    for (int mf = 0; mf < 2; mf++) {
        int r0 = bm + warpM * 32 + mf * 16 + g;
        float s0 = 0.f, d0 = 0.f, s1 = 0.f, d1 = 0.f;  // rows r0, r0+8
        #pragma unroll
        for (int nf = 0; nf < NF; nf++) {
            int cc = warpN * (NF * 8) + nf * 8 + t4 * 2;
            int ic = chbase + nf * 8 + t4 * 2;
            float w_s0 = a_s[head * 64 + ic],     w_s1 = a_s[head * 64 + ic + 1];
            float w_d0 = a_d[head * 64 + ic],     w_d1 = a_d[head * 64 + ic + 1];
            s0 += acc[mf][nf][0] * w_s0 + acc[mf][nf][1] * w_s1;
            d0 += acc[mf][nf][0] * w_d0 + acc[mf][nf][1] * w_d1;
            s1 += acc[mf][nf][2] * w_s0 + acc[mf][nf][3] * w_s1;
            d1 += acc[mf][nf][2] * w_d0 + acc[mf][nf][3] * w_d1;

            int col = bn + cc;
            if (r0 < M)
                *(__half2*)(C + (size_t)r0 * Nc + col) =
                    __floats2half2_rn(acc[mf][nf][0], acc[mf][nf][1]);
            if (r0 + 8 < M)
                *(__half2*)(C + (size_t)(r0 + 8) * Nc + col) =
                    __floats2half2_rn(acc[mf][nf][2], acc[mf][nf][3]);
        }
        #pragma unroll
        for (int o = 1; o <= 2; o <<= 1) {
            s0 += __shfl_xor_sync(0xffffffffu, s0, o);
            d0 += __shfl_xor_sync(0xffffffffu, d0, o);
            s1 += __shfl_xor_sync(0xffffffffu, s1, o);
            d1 += __shfl_xor_sync(0xffffffffu, d1, o);
        }
        if (t4 == 0) {
            if (r0 < M) {
                atomicAdd(&as_out[r0 * H + head], s0);
                atomicAdd(&ad_out[r0 * H + head], d0);
            }
            if (r0 + 8 < M) {
                atomicAdd(&as_out[(r0 + 8) * H + head], s1);
                atomicAdd(&ad_out[(r0 + 8) * H + head], d1);
            }
        }
    }
}

// -------- aggregation: one warp per dst node, online-softmax CSR walk --------
// h gathered in fp16 (16 B per lane per edge, H=4); fp32 accumulate + output.
template <int H>
__global__ __launch_bounds__(256) void aggregate_kernel(
    const float* __restrict__ as_, const float* __restrict__ ad_,
    const __half* __restrict__ h,
    const float* __restrict__ b, float* __restrict__ outp, int relu)
{
    const int F = H * 64;
    const int VEC = F / 32;  // 8 (H=4) or 2 (H=1)
    int gtid = blockIdx.x * blockDim.x + threadIdx.x;
    int node = gtid >> 5;
    int lane = threadIdx.x & 31;
    if (node >= NN) return;
    int hh = (lane * VEC) >> 6;
    float adv = ad_[node * H + hh];
    int i0 = g_off[node], i1 = g_off[node + 1];

    float m = -1e30f, den = 0.f;
    float acc[VEC] = {};
    for (int i = i0; i < i1; i++) {
        int s = g_csrc[i];
        float x = as_[s * H + hh] + adv;
        x = x > 0.f ? x : 0.2f * x;
        if (x > m) {
            float r = __expf(m - x);
            den *= r;
            #pragma unroll
            for (int j = 0; j < VEC; j++) acc[j] *= r;
            m = x;
        }
        float ex = __expf(x - m);
        den += ex;
        const __half* hp = h + (size_t)s * F + lane * VEC;
        if (VEC == 8) {
            uint4 u = *(const uint4*)hp;
            float2 f0 = __half22float2(*(__half2*)&u.x);
            float2 f1 = __half22float2(*(__half2*)&u.y);
            float2 f2 = __half22float2(*(__half2*)&u.z);
            float2 f3 = __half22float2(*(__half2*)&u.w);
            acc[0] += ex * f0.x; acc[1] += ex * f0.y;
            acc[2] += ex * f1.x; acc[3] += ex * f1.y;
            acc[4] += ex * f2.x; acc[5] += ex * f2.y;
            acc[6] += ex * f3.x; acc[7] += ex * f3.y;
        } else {
            unsigned u = *(const unsigned*)hp;
            float2 f = __half22float2(*(__half2*)&u);
            acc[0] += ex * f.x; acc[1] += ex * f.y;
        }
    }
    float inv = 1.f / (den + 1e-16f);
    float* op = outp + (size_t)node * F + lane * VEC;
    #pragma unroll
    for (int j = 0; j < VEC; j++) {
        float v = acc[j] * inv + b[lane * VEC + j];
        if (relu) v = v > 0.f ? v : 0.f;
        op[j] = v;
    }
}

// -------- mean pool + head --------
__global__ void zero_pool_kernel(float* __restrict__ g) { g[threadIdx.x] = 0.f; }

__global__ void reduce_kernel(const float* __restrict__ h, float* __restrict__ g)
{
    int col = threadIdx.x & 63;
    float s = 0.f;
    for (int r = blockIdx.x * 4 + (threadIdx.x >> 6); r < NN; r += gridDim.x * 4)
        s += h[(size_t)r * 64 + col];
    atomicAdd(&g[col], s);
}

__global__ void head_kernel(const float* __restrict__ g, const float* __restrict__ hw,
                            const float* __restrict__ hb, float* __restrict__ out)
{
    int j = threadIdx.x;  // 64
    float s = 0.f;
    const float inv = 1.f / (float)NN;
    #pragma unroll 8
    for (int c = 0; c < 64; c++)
        s += (g[c] * inv) * hw[c * 64 + j];
    out[j] = s + hb[j];
}

extern "C" void kernel_launch(void* const* d_in, const int* in_sizes, int n_in,
                              void* d_out, int out_size)
{
    (void)in_sizes; (void)n_in; (void)out_size;
    const float* x   = (const float*)d_in[0];
    const int*   ei  = (const int*)d_in[1];
    const float* W0  = (const float*)d_in[2];
    const float* a0s = (const float*)d_in[3];
    const float* a0d = (const float*)d_in[4];
    const float* b0  = (const float*)d_in[5];
    const float* W1  = (const float*)d_in[6];
    const float* a1s = (const float*)d_in[7];
    const float* a1d = (const float*)d_in[8];
    const float* b1  = (const float*)d_in[9];
    const float* W2  = (const float*)d_in[10];
    const float* a2s = (const float*)d_in[11];
    const float* a2d = (const float*)d_in[12];
    const float* b2  = (const float*)d_in[13];
    const float* hw  = (const float*)d_in[14];
    const float* hb  = (const float*)d_in[15];
    float* out = (float*)d_out;

    __half* hbuf;
    float *bufB, *as_, *ad_, *pool;
    cudaGetSymbolAddress((void**)&hbuf, g_hb);
    cudaGetSymbolAddress((void**)&bufB, g_bufB);
    cudaGetSymbolAddress((void**)&as_,  g_as);
    cudaGetSymbolAddress((void**)&ad_,  g_ad);
    cudaGetSymbolAddress((void**)&pool, g_pool);

    // CSR prelude + layer-0 GEMM early so gemm0 lands in the profiled slot
    detect_kernel<<<1, 256>>>(ei);
    zero_cnt_alpha_kernel<<<(NN * 4 + 255) / 256, 256>>>();
    decode_kernel<<<(ENE + 255) / 256, 256>>>(ei);

    // Layer 0 GEMM: x[N,128] @ W0 -> hbuf[N,256] fp16, fused alpha (BN=128)
    {
        dim3 grid(2, (NN + 127) / 128);
        gemm_f16_kernel<8><<<grid, 256>>>(x, W0, hbuf, NN, 128, 256, a0s, a0d, as_, ad_, 4);
    }

    block_sum_kernel<<<SCAN_B, 256>>>();
    scan_bsum_kernel<<<1, 256>>>();
    scan_final_kernel<<<SCAN_B, 256>>>();
    scatter_kernel<<<(ENE + 255) / 256, 256>>>();

    aggregate_kernel<4><<<(NN * 32 + 255) / 256, 256>>>(as_, ad_, hbuf, b0, bufB, 1);

    // Layer 1
    zero_alpha_kernel<<<(NN * 4 + 255) / 256, 256>>>(as_, ad_, NN * 4);
    {
        dim3 grid(2, (NN + 127) / 128);
        gemm_f16_kernel<8><<<grid, 256>>>(bufB, W1, hbuf, NN, 256, 256, a1s, a1d, as_, ad_, 4);
    }
    aggregate_kernel<4><<<(NN * 32 + 255) / 256, 256>>>(as_, ad_, hbuf, b1, bufB, 1);

    // Layer 2 (H=1, Nc=64 -> NF=4 shape)
    zero_alpha_kernel<<<(NN + 255) / 256, 256>>>(as_, ad_, NN);
    {
        dim3 grid(1, (NN + 127) / 128);
        gemm_f16_kernel<4><<<grid, 256>>>(bufB, W2, hbuf, NN, 256, 64, a2s, a2d, as_, ad_, 1);
    }
    aggregate_kernel<1><<<(NN * 32 + 255) / 256, 256>>>(as_, ad_, hbuf, b2, bufB, 0);

    zero_pool_kernel<<<1, 64>>>(pool);
    reduce_kernel<<<256, 256>>>(bufB, pool);
    head_kernel<<<1, 64>>>(pool, hw, hb, out);
}